// round 16
// baseline (speedup 1.0000x reference)
#include <cuda_runtime.h>
#include <cstdint>

#define NB 16
#define CI 64
#define CO 64
#define HH 128
#define WW 128
#define TH 8
#define TW 32
#define NTHREADS 256
#define NCHUNK 8                    // 8 channels per chunk (k32)
#define HW (HH*WW)

// smem: W fp16 [16 k16-blocks][64o][32B] + A fp16 double-buffered
#define WH_OFF 0
#define AH_OFF 32768                // 2 chunk-bufs * 16384
#define SMEM_BYTES (AH_OFF+32768)   // 65536 -> 2 CTAs/SM (reg-capped anyway)

// k-major 32B rows; 16B-unit XOR swizzle -> conflict-free ldmatrix/STS
#define SWZ(row, half) (((((row)*2+(half)) ^ (((row)>>2)&1)))*16)

// pack two f32 -> f16x2 (lo = a, hi = b), rn-even
__device__ __forceinline__ uint32_t pf16(float a, float b){
    uint32_t pk;
    asm("cvt.rn.f16x2.f32 %0, %1, %2;" : "=r"(pk) : "f"(b), "f"(a));
    return pk;
}
__device__ __forceinline__ void ldm4(uint32_t* r, uint32_t addr){
    asm volatile("ldmatrix.sync.aligned.m8n8.x4.shared.b16 {%0,%1,%2,%3}, [%4];"
                 : "=r"(r[0]), "=r"(r[1]), "=r"(r[2]), "=r"(r[3]) : "r"(addr));
}
__device__ __forceinline__ void mma16816(float* d, const uint32_t* a, uint32_t b0, uint32_t b1){
    asm volatile("mma.sync.aligned.m16n8k16.row.col.f32.f16.f16.f32 "
                 "{%0,%1,%2,%3}, {%4,%5,%6,%7}, {%8,%9}, {%0,%1,%2,%3};"
                 : "+f"(d[0]), "+f"(d[1]), "+f"(d[2]), "+f"(d[3])
                 : "r"(a[0]), "r"(a[1]), "r"(a[2]), "r"(a[3]), "r"(b0), "r"(b1));
}
__device__ __forceinline__ float ldg_or0(const float* p, bool ok){
    return ok ? __ldg(p) : 0.f;
}

__global__ __launch_bounds__(NTHREADS, 2)
void steered_mma(const float* __restrict__ x, const float* __restrict__ theta,
                 const float* __restrict__ wts, const float* __restrict__ bias,
                 float* __restrict__ out)
{
    extern __shared__ float smf[];
    char* sm = (char*)smf;
    const unsigned sb = (unsigned)__cvta_generic_to_shared(sm);
    const int tid = threadIdx.x;
    const int lane = tid & 31, warp = tid >> 5;
    const int n = blockIdx.z, h0 = blockIdx.y*TH, w0 = blockIdx.x*TW;
    const float* xb = x + (size_t)n*CI*HW;

    // ---- W preprocessing: wts[o][i][4] -> W[k16-block][o][k16] fp16, swizzled ----
    #pragma unroll 4
    for (int t = 0; t < 16; t++){
        int e = tid + t*256;
        int o = e & 63, i = e >> 6;
        float4 v = ((const float4*)wts)[o*64 + i];     // w[o][i][0..3]
        int cc = i >> 2, j = i & 3;
        uint32_t h0u = pf16(v.x, v.y);
        uint32_t h1u = pf16(v.z, v.w);
        int off = cc*2048 + SWZ(o, (j>>1)) + (j&1)*8;
        *(uint2*)(sm + WH_OFF + off) = make_uint2(h0u, h1u);
    }

    // ---- per-pixel harmonics + tap addressing (pixel: row h0+warp, col w0+lane) ----
    const int gh = h0 + warp, gw = w0 + lane;
    float th = theta[((size_t)n*HH + gh)*WW + gw];
    float s1, c1;
    sincosf(6.28318530717958647692f * th, &s1, &c1);
    const float c2 = 2.f*c1*c1 - 1.f, s2 = 2.f*s1*c1;
    const float cps = c1 + s1, cms = c1 - s1;
    const float Q = 0.35355339059327376220f;     // 1/(2*sqrt(2))

    const bool vr0 = (gh > 0), vr2 = (gh < HH-1);
    const bool vc0 = (gw > 0), vc2 = (gw < WW-1);
    const bool v00 = vr0 && vc0, v02 = vr0 && vc2;
    const bool v20 = vr2 && vc0, v22 = vr2 && vc2;
    const int base = gh*WW + gw;

    // ---- per-lane ldmatrix addresses ----
    uint32_t aswz0 = SWZ(warp*32 +      (lane & 15), (lane >> 4));
    uint32_t aswz1 = SWZ(warp*32 + 16 + (lane & 15), (lane >> 4));
    const int olc = (lane & 7) + ((lane >> 4) << 3);
    const int whalf = (lane >> 3) & 1;
    uint32_t wswz[4];
    #pragma unroll
    for (int np = 0; np < 4; np++) wswz[np] = SWZ(np*16 + olc, whalf);

    float acc[2][8][4];
    #pragma unroll
    for (int a = 0; a < 2; a++)
        #pragma unroll
        for (int b = 0; b < 8; b++)
            #pragma unroll
            for (int q = 0; q < 4; q++) acc[a][b][q] = 0.f;

    __syncthreads();         // W visible; ONLY CTA barrier before epilogue

    for (int c = 0; c < NCHUNK; c++){
        // ---- build A(c): 8 channels x 4 harmonics, taps via direct LDG ----
        char* abuf_w = sm + AH_OFF + (c & 1)*16384;
        #pragma unroll
        for (int kk = 0; kk < 2; kk++){
            uint32_t hu[8];
            #pragma unroll
            for (int jj = 0; jj < 4; jj++){
                const float* xc = xb + (size_t)(c*8 + kk*4 + jj)*HW + base;
                float t0 = ldg_or0(xc - WW - 1, v00);
                float t1 = ldg_or0(xc - WW,     vr0);
                float t2 = ldg_or0(xc - WW + 1, v02);
                float t3 = ldg_or0(xc - 1,      vc0);
                float t4 = __ldg(xc);
                float t5 = ldg_or0(xc + 1,      vc2);
                float t6 = ldg_or0(xc + WW - 1, v20);
                float t7 = ldg_or0(xc + WW,     vr2);
                float t8 = ldg_or0(xc + WW + 1, v22);
                float ring = ((t0+t1)+(t2+t3)) + ((t5+t6)+(t7+t8));
                float z2 = Q*(cps*(t8-t0) + cms*(t2-t6)) + 0.5f*(c1*(t5-t3) + s1*(t7-t1));
                float z3 = 0.5f*(s2*((t0+t8)-(t2+t6)) + c2*((t3+t5)-(t1+t7)));
                hu[jj*2]   = pf16(t4, Q*ring);
                hu[jj*2+1] = pf16(z2, z3);
            }
            char* ah = abuf_w + kk*8192;
            *(uint4*)(ah + SWZ(tid,0)) = make_uint4(hu[0],hu[1],hu[2],hu[3]);
            *(uint4*)(ah + SWZ(tid,1)) = make_uint4(hu[4],hu[5],hu[6],hu[7]);
        }
        __syncwarp();        // A rows warp-private: STS -> ldmatrix visibility only

        // ---- tensor-core GEMM: 2 k16 blocks ----
        const unsigned abuf = sb + AH_OFF + (unsigned)(c & 1)*16384u;
        #pragma unroll
        for (int kk = 0; kk < 2; kk++){
            uint32_t ahf[2][4];
            ldm4(ahf[0], abuf + (unsigned)kk*8192u + aswz0);
            ldm4(ahf[1], abuf + (unsigned)kk*8192u + aswz1);
            uint32_t wh_base = sb + WH_OFF + (unsigned)(2*c + kk)*2048u;
            #pragma unroll
            for (int np = 0; np < 4; np++){
                uint32_t bh[4];
                ldm4(bh, wh_base + wswz[np]);
                #pragma unroll
                for (int s = 0; s < 2; s++){
                    #pragma unroll
                    for (int mt = 0; mt < 2; mt++)
                        mma16816(acc[mt][np*2 + s], ahf[mt], bh[s*2], bh[s*2+1]);
                }
            }
        }
    }

    // ---- epilogue: bias + store ----
    const int gr = lane >> 2, tg = lane & 3;
    float* ob = out + (size_t)n*CO*HW;
    #pragma unroll
    for (int mt = 0; mt < 2; mt++){
        size_t off0 = (size_t)gh*WW + (w0 + mt*16 + gr);
        size_t off1 = off0 + 8;
        #pragma unroll
        for (int nt = 0; nt < 8; nt++){
            int o = nt*8 + tg*2;
            float b0v = __ldg(bias + o);
            float b1v = __ldg(bias + o + 1);
            ob[(size_t)o*HW     + off0] = acc[mt][nt][0] + b0v;
            ob[(size_t)(o+1)*HW + off0] = acc[mt][nt][1] + b1v;
            ob[(size_t)o*HW     + off1] = acc[mt][nt][2] + b0v;
            ob[(size_t)(o+1)*HW + off1] = acc[mt][nt][3] + b1v;
        }
    }
}

extern "C" void kernel_launch(void* const* d_in, const int* in_sizes, int n_in,
                              void* d_out, int out_size) {
    const float* x     = (const float*)d_in[0];
    const float* theta = (const float*)d_in[1];
    const float* wts   = (const float*)d_in[2];
    const float* bias  = (const float*)d_in[3];
    float* out = (float*)d_out;

    cudaFuncSetAttribute(steered_mma,
                         cudaFuncAttributeMaxDynamicSharedMemorySize, SMEM_BYTES);
    dim3 grid(WW/TW, HH/TH, NB);
    steered_mma<<<grid, NTHREADS, SMEM_BYTES>>>(x, theta, wts, bias, out);
}

// round 17
// speedup vs baseline: 2.1057x; 2.1057x over previous
#include <cuda_runtime.h>
#include <cstdint>

#define NB 16
#define CI 64
#define CO 64
#define HH 128
#define WW 128
#define TH 8
#define TW 32
#define NTHREADS 256
#define NCHUNK 8                    // 8 channels per chunk (k32)
#define HW (HH*WW)

// staged x tile: per channel 10 rows x 40 floats ([w0-4, w0+36))
#define XROW 40
#define XS_CH (10*XROW)             // 400 floats
#define XS_CHUNK (8*XS_CH)          // 3200 floats per chunk
#define NSEG (8*10*10)              // 800 16B segments per chunk

// smem byte offsets (GEMM bases 128B-aligned)
#define XB_OFF 0                    // 3 bufs * 12800B = 38400
#define WH_OFF 38400                // W fp16: 16 k16-blocks * 64o * 32B = 32768
#define AH_OFF (WH_OFF+32768)       // 71168: A fp16, 2 chunk-bufs * 16384
#define SMEM_BYTES (AH_OFF+32768)   // 103936 -> 2 CTAs/SM

// epilogue restage: per-warp [64 o][stride 36 floats], base reuses whole smem
#define EPI_WARP_FLOATS (64*36)     // 2304 floats = 9216 B per warp (8*9216=73728 <= 103936)

// k-major 32B rows; 16B-unit XOR swizzle -> conflict-free ldmatrix/STS
#define SWZ(row, half) (((((row)*2+(half)) ^ (((row)>>2)&1)))*16)

// pack two f32 -> f16x2 (lo = a, hi = b), rn-even
__device__ __forceinline__ uint32_t pf16(float a, float b){
    uint32_t pk;
    asm("cvt.rn.f16x2.f32 %0, %1, %2;" : "=r"(pk) : "f"(b), "f"(a));
    return pk;
}
__device__ __forceinline__ void ldm4(uint32_t* r, uint32_t addr){
    asm volatile("ldmatrix.sync.aligned.m8n8.x4.shared.b16 {%0,%1,%2,%3}, [%4];"
                 : "=r"(r[0]), "=r"(r[1]), "=r"(r[2]), "=r"(r[3]) : "r"(addr));
}
__device__ __forceinline__ void mma16816(float* d, const uint32_t* a, uint32_t b0, uint32_t b1){
    asm volatile("mma.sync.aligned.m16n8k16.row.col.f32.f16.f16.f32 "
                 "{%0,%1,%2,%3}, {%4,%5,%6,%7}, {%8,%9}, {%0,%1,%2,%3};"
                 : "+f"(d[0]), "+f"(d[1]), "+f"(d[2]), "+f"(d[3])
                 : "r"(a[0]), "r"(a[1]), "r"(a[2]), "r"(a[3]), "r"(b0), "r"(b1));
}

// vectorized 16B x loader with hoisted addressing: soff<0 marks OOB (zero-fill)
__device__ __forceinline__ void load_chunk_vec(const float* __restrict__ xb, int ch, int buf,
                                               int tid, unsigned sb, const int* soff){
    unsigned dbase = sb + (unsigned)XB_OFF + (unsigned)buf*(XS_CHUNK*4u);
    const float* xc = xb + (size_t)(ch*8) * HW;
    #pragma unroll
    for (int k = 0; k < 4; k++){
        int e = tid + k*256;
        if (k < 3 || tid < (NSEG - 3*256)){
            int so = soff[k];
            const float* src = (so >= 0) ? (xc + so) : xb;
            int sz = (so >= 0) ? 16 : 0;
            asm volatile("cp.async.cg.shared.global [%0], [%1], 16, %2;"
                         :: "r"(dbase + (unsigned)e*16u), "l"(src), "r"(sz));
        }
    }
}

// build A chunk (warp-local row tid): 8 ch x 4 harmonics -> fp16, swizzled STS
__device__ __forceinline__ void build_A(char* sm, const float* xsb, int abuf_off, int tid, int ctr,
                                        float c1, float s1, float c2, float s2,
                                        float cps, float cms){
    const float Q = 0.35355339059327376220f;     // 1/(2*sqrt(2))
    #pragma unroll
    for (int kk = 0; kk < 2; kk++){
        uint32_t hu[8];
        #pragma unroll
        for (int jj = 0; jj < 4; jj++){
            const float* xp = xsb + (kk*4 + jj)*XS_CH + ctr;
            float t0=xp[-XROW-1], t1=xp[-XROW], t2=xp[-XROW+1];
            float t3=xp[-1],      t4=xp[0],     t5=xp[1];
            float t6=xp[XROW-1],  t7=xp[XROW],  t8=xp[XROW+1];
            float ring = ((t0+t1)+(t2+t3)) + ((t5+t6)+(t7+t8));
            float z2 = Q*(cps*(t8-t0) + cms*(t2-t6)) + 0.5f*(c1*(t5-t3) + s1*(t7-t1));
            float z3 = 0.5f*(s2*((t0+t8)-(t2+t6)) + c2*((t3+t5)-(t1+t7)));
            hu[jj*2]   = pf16(t4, Q*ring);
            hu[jj*2+1] = pf16(z2, z3);
        }
        char* ah = sm + AH_OFF + abuf_off + kk*8192;
        *(uint4*)(ah + SWZ(tid,0)) = make_uint4(hu[0],hu[1],hu[2],hu[3]);
        *(uint4*)(ah + SWZ(tid,1)) = make_uint4(hu[4],hu[5],hu[6],hu[7]);
    }
}

__global__ __launch_bounds__(NTHREADS, 2)
void steered_mma(const float* __restrict__ x, const float* __restrict__ theta,
                 const float* __restrict__ wts, const float* __restrict__ bias,
                 float* __restrict__ out)
{
    extern __shared__ float smf[];
    char* sm = (char*)smf;
    const unsigned sb = (unsigned)__cvta_generic_to_shared(sm);
    const int tid = threadIdx.x;
    const int lane = tid & 31, warp = tid >> 5;
    const int n = blockIdx.z, h0 = blockIdx.y*TH, w0 = blockIdx.x*TW;
    const float* xb = x + (size_t)n*CI*HW;

    // ---- hoisted per-thread 16B-segment addressing (chunk-invariant) ----
    int soff[4];
    #pragma unroll
    for (int k = 0; k < 4; k++){
        int e = tid + k*256;
        int j = e / 100; int rem = e - j*100;
        int r = rem / 10;  int s = rem - r*10;
        int gh = h0 - 1 + r;
        int gw = w0 - 4 + s*4;
        bool v = (e < NSEG) && ((unsigned)gh < (unsigned)HH) && ((unsigned)gw < (unsigned)WW);
        soff[k] = v ? (j*HW + gh*WW + gw) : -1;
    }

    // prefetch x chunks 0,1 into bufs 0,1
    load_chunk_vec(xb, 0, 0, tid, sb, soff);
    asm volatile("cp.async.commit_group;" ::: "memory");
    load_chunk_vec(xb, 1, 1, tid, sb, soff);
    asm volatile("cp.async.commit_group;" ::: "memory");

    // ---- W preprocessing: wts[o][i][4] -> W[k16-block][o][k16] fp16, swizzled ----
    #pragma unroll 4
    for (int t = 0; t < 16; t++){
        int e = tid + t*256;
        int o = e & 63, i = e >> 6;
        float4 v = ((const float4*)wts)[o*64 + i];     // w[o][i][0..3]
        int cc = i >> 2, j = i & 3;
        uint32_t h0u = pf16(v.x, v.y);
        uint32_t h1u = pf16(v.z, v.w);
        int off = cc*2048 + SWZ(o, (j>>1)) + (j&1)*8;
        *(uint2*)(sm + WH_OFF + off) = make_uint2(h0u, h1u);
    }

    // ---- per-pixel harmonics (pixel: row h0+warp, col w0+lane... tid-mapped) ----
    const int py = tid >> 5, px = tid & 31;
    float th = theta[((size_t)n*HH + (h0+py))*WW + (w0+px)];
    float s1, c1;
    sincosf(6.28318530717958647692f * th, &s1, &c1);
    const float c2 = 2.f*c1*c1 - 1.f, s2 = 2.f*s1*c1;
    const float cps = c1 + s1, cms = c1 - s1;
    const int ctr = (py+1)*XROW + (px+4);        // center tap in staged tile

    // ---- per-lane ldmatrix swizzle offsets ----
    uint32_t aswz0 = SWZ(warp*32 +      (lane & 15), (lane >> 4));
    uint32_t aswz1 = SWZ(warp*32 + 16 + (lane & 15), (lane >> 4));
    const int olc = (lane & 7) + ((lane >> 4) << 3);
    const int whalf = (lane >> 3) & 1;
    uint32_t wswz[4];
    #pragma unroll
    for (int np = 0; np < 4; np++) wswz[np] = SWZ(np*16 + olc, whalf);

    float acc[2][8][4];
    #pragma unroll
    for (int a = 0; a < 2; a++)
        #pragma unroll
        for (int b = 0; b < 8; b++)
            #pragma unroll
            for (int q = 0; q < 4; q++) acc[a][b][q] = 0.f;

    // ---- pipeline prologue: X(0) ready -> build A(0) into buf 0 ----
    asm volatile("cp.async.wait_group 1;" ::: "memory");   // X(0) complete
    __syncthreads();                                       // X(0) visible CTA-wide
    build_A(sm, smf + 0*XS_CHUNK, 0, tid, ctr, c1, s1, c2, s2, cps, cms);
    load_chunk_vec(xb, 2, 2, tid, sb, soff);               // prefetch X(2) -> buf 2
    asm volatile("cp.async.commit_group;" ::: "memory");

    for (int c = 0; c < NCHUNK; c++){
        __syncwarp();            // A(c) STS (warp-private rows) -> ldmatrix visibility

        const unsigned abuf = sb + AH_OFF + (unsigned)(c & 1)*16384u;
        uint32_t ahf0[2][4];     // kk=0 fragments, loaded before the overlapped build
        ldm4(ahf0[0], abuf + aswz0);
        ldm4(ahf0[1], abuf + aswz1);

        if (c < NCHUNK-1){
            // make X(c+1) visible; prefetch X(c+3); build A(c+1) (overlaps GEMM below)
            if (c < NCHUNK-2) asm volatile("cp.async.wait_group 1;" ::: "memory");
            else              asm volatile("cp.async.wait_group 0;" ::: "memory");
            __syncthreads();     // X(c+1) visible; all reads of X-buf c%3 retired
            if (c + 3 < NCHUNK){
                int wb = c % 3;  // (c+3)%3
                load_chunk_vec(xb, c+3, wb, tid, sb, soff);
                asm volatile("cp.async.commit_group;" ::: "memory");
            }
            build_A(sm, smf + ((c+1)%3)*XS_CHUNK, ((c+1)&1)*16384, tid, ctr,
                    c1, s1, c2, s2, cps, cms);
        }

        // ---- GEMM kk=0 ----
        {
            uint32_t wh_base = sb + WH_OFF + (unsigned)(2*c)*2048u;
            #pragma unroll
            for (int np = 0; np < 4; np++){
                uint32_t bh[4];
                ldm4(bh, wh_base + wswz[np]);
                #pragma unroll
                for (int s = 0; s < 2; s++){
                    #pragma unroll
                    for (int mt = 0; mt < 2; mt++)
                        mma16816(acc[mt][np*2 + s], ahf0[mt], bh[s*2], bh[s*2+1]);
                }
            }
        }
        // ---- GEMM kk=1 ----
        {
            uint32_t ahf1[2][4];
            ldm4(ahf1[0], abuf + 8192u + aswz0);
            ldm4(ahf1[1], abuf + 8192u + aswz1);
            uint32_t wh_base = sb + WH_OFF + (unsigned)(2*c + 1)*2048u;
            #pragma unroll
            for (int np = 0; np < 4; np++){
                uint32_t bh[4];
                ldm4(bh, wh_base + wswz[np]);
                #pragma unroll
                for (int s = 0; s < 2; s++){
                    #pragma unroll
                    for (int mt = 0; mt < 2; mt++)
                        mma16816(acc[mt][np*2 + s], ahf1[mt], bh[s*2], bh[s*2+1]);
                }
            }
        }
    }

    // ---- epilogue: restage through smem for coalesced stores ----
    __syncthreads();            // all X/W/A smem reads retired; whole smem reusable
    {
        float* ep = smf + warp*EPI_WARP_FLOATS;   // warp-private [64 o][stride 36]
        const int gr = lane >> 2, tg = lane & 3;
        // phase 1: scatter acc (+bias) into [o][col] stride-36 (conflict-free STS)
        #pragma unroll
        for (int mt = 0; mt < 2; mt++){
            #pragma unroll
            for (int nt = 0; nt < 8; nt++){
                int o = nt*8 + tg*2;
                float b0v = __ldg(bias + o);
                float b1v = __ldg(bias + o + 1);
                int col0 = mt*16 + gr;
                ep[o*36     + col0]     = acc[mt][nt][0] + b0v;
                ep[(o+1)*36 + col0]     = acc[mt][nt][1] + b1v;
                ep[o*36     + col0 + 8] = acc[mt][nt][2] + b0v;
                ep[(o+1)*36 + col0 + 8] = acc[mt][nt][3] + b1v;
            }
        }
        __syncwarp();
        // phase 2: coalesced row stores (128B per o-row)
        float* ob = out + (size_t)n*CO*HW + (size_t)(h0 + warp)*WW + w0;
        #pragma unroll 8
        for (int o = 0; o < 64; o++){
            ob[(size_t)o*HW + lane] = ep[o*36 + lane];
        }
    }
}

extern "C" void kernel_launch(void* const* d_in, const int* in_sizes, int n_in,
                              void* d_out, int out_size) {
    const float* x     = (const float*)d_in[0];
    const float* theta = (const float*)d_in[1];
    const float* wts   = (const float*)d_in[2];
    const float* bias  = (const float*)d_in[3];
    float* out = (float*)d_out;

    cudaFuncSetAttribute(steered_mma,
                         cudaFuncAttributeMaxDynamicSharedMemorySize, SMEM_BYTES);
    dim3 grid(WW/TW, HH/TH, NB);
    steered_mma<<<grid, NTHREADS, SMEM_BYTES>>>(x, theta, wts, bias, out);
}